// round 5
// baseline (speedup 1.0000x reference)
#include <cuda_runtime.h>
#include <cstdint>

#define D_MODEL 1024
#define KV_DIM 256
#define N_HEADS 16
#define HEAD_DIM 64
#define TSEQ 2048
#define BATCH 2
#define BT (BATCH * TSEQ)

// Scratch (device globals; no allocation anywhere).
__device__ float g_Q[(size_t)BT * D_MODEL];
__device__ float g_K[(size_t)BT * KV_DIM];
__device__ float g_V[(size_t)BT * KV_DIM];
__device__ float g_O[(size_t)BT * D_MODEL];

// ---------------------------------------------------------------------------
// Helpers
// ---------------------------------------------------------------------------
__device__ __forceinline__ float f2tf32(float v) {
    uint32_t u; asm("cvt.rna.tf32.f32 %0, %1;" : "=r"(u) : "f"(v));
    return __uint_as_float(u);
}

__device__ __forceinline__ void mma1688(float* d, float a0, float a1, float a2,
                                        float a3, float b0, float b1) {
    asm volatile(
        "mma.sync.aligned.m16n8k8.row.col.f32.tf32.tf32.f32 "
        "{%0,%1,%2,%3}, {%4,%5,%6,%7}, {%8,%9}, {%0,%1,%2,%3};"
        : "+f"(d[0]), "+f"(d[1]), "+f"(d[2]), "+f"(d[3])
        : "r"(__float_as_uint(a0)), "r"(__float_as_uint(a1)),
          "r"(__float_as_uint(a2)), "r"(__float_as_uint(a3)),
          "r"(__float_as_uint(b0)), "r"(__float_as_uint(b1)));
}

// ---------------------------------------------------------------------------
// 3xTF32 mma.sync GEMM tile: C[128,128] at (m0,n0) = A @ W + bias
// 256 threads (8 warps, 2x4), 64x32 warp tile, K-chunk 32.
// ---------------------------------------------------------------------------
#define AST 36
#define BST 132
#define SM_AH 0
#define SM_AL (128 * AST)
#define SM_BH (2 * 128 * AST)
#define SM_BL (2 * 128 * AST + 32 * BST)
#define SM_FLOATS (2 * 128 * AST + 2 * 32 * BST)

__device__ __forceinline__ void gemm_tile(
    const float* __restrict__ A, const float* __restrict__ W,
    const float* __restrict__ bias, float* __restrict__ C,
    int N, int K, int m0, int n0)
{
    extern __shared__ float s[];

    const int tid = threadIdx.x;
    const int lane = tid & 31;
    const int wid = tid >> 5;
    const int wm = (wid >> 2) * 64;
    const int wn = (wid & 3) * 32;
    const int lr = lane >> 2;
    const int lc = lane & 3;

    const int arow = tid >> 1;
    const int ac0 = (tid & 1) * 16;
    const int brow = tid >> 3;
    const int bc0 = (tid & 7) * 16;

    float acc[4][4][4];
#pragma unroll
    for (int i = 0; i < 4; i++)
#pragma unroll
        for (int j = 0; j < 4; j++)
#pragma unroll
            for (int k = 0; k < 4; k++) acc[i][j][k] = 0.0f;

    const float* Ar = A + (size_t)(m0 + arow) * K;

    for (int kc = 0; kc < K; kc += 32) {
        __syncthreads();
#pragma unroll
        for (int i = 0; i < 4; i++) {
            float4 v = *(const float4*)(Ar + kc + ac0 + i * 4);
            float hx = f2tf32(v.x), hy = f2tf32(v.y),
                  hz = f2tf32(v.z), hw = f2tf32(v.w);
            const int o = arow * AST + ac0 + i * 4;
            s[SM_AH + o + 0] = hx; s[SM_AL + o + 0] = f2tf32(v.x - hx);
            s[SM_AH + o + 1] = hy; s[SM_AL + o + 1] = f2tf32(v.y - hy);
            s[SM_AH + o + 2] = hz; s[SM_AL + o + 2] = f2tf32(v.z - hz);
            s[SM_AH + o + 3] = hw; s[SM_AL + o + 3] = f2tf32(v.w - hw);
        }
#pragma unroll
        for (int i = 0; i < 4; i++) {
            float4 v = *(const float4*)(W + (size_t)(kc + brow) * N + n0 + bc0 + i * 4);
            float hx = f2tf32(v.x), hy = f2tf32(v.y),
                  hz = f2tf32(v.z), hw = f2tf32(v.w);
            const int o = brow * BST + bc0 + i * 4;
            s[SM_BH + o + 0] = hx; s[SM_BL + o + 0] = f2tf32(v.x - hx);
            s[SM_BH + o + 1] = hy; s[SM_BL + o + 1] = f2tf32(v.y - hy);
            s[SM_BH + o + 2] = hz; s[SM_BL + o + 2] = f2tf32(v.z - hz);
            s[SM_BH + o + 3] = hw; s[SM_BL + o + 3] = f2tf32(v.w - hw);
        }
        __syncthreads();

#pragma unroll
        for (int kk = 0; kk < 4; kk++) {
            const int kb = kk * 8;
            float bh[4][2], bl[4][2];
#pragma unroll
            for (int nt = 0; nt < 4; nt++) {
                const int n = wn + nt * 8 + lr;
                bh[nt][0] = s[SM_BH + (kb + lc) * BST + n];
                bh[nt][1] = s[SM_BH + (kb + 4 + lc) * BST + n];
                bl[nt][0] = s[SM_BL + (kb + lc) * BST + n];
                bl[nt][1] = s[SM_BL + (kb + 4 + lc) * BST + n];
            }
#pragma unroll
            for (int mt = 0; mt < 4; mt++) {
                const int m = wm + mt * 16 + lr;
                float ah0 = s[SM_AH + m * AST + kb + lc];
                float ah1 = s[SM_AH + (m + 8) * AST + kb + lc];
                float ah2 = s[SM_AH + m * AST + kb + 4 + lc];
                float ah3 = s[SM_AH + (m + 8) * AST + kb + 4 + lc];
                float al0 = s[SM_AL + m * AST + kb + lc];
                float al1 = s[SM_AL + (m + 8) * AST + kb + lc];
                float al2 = s[SM_AL + m * AST + kb + 4 + lc];
                float al3 = s[SM_AL + (m + 8) * AST + kb + 4 + lc];
#pragma unroll
                for (int nt = 0; nt < 4; nt++) {
                    mma1688(acc[mt][nt], ah0, ah1, ah2, ah3, bh[nt][0], bh[nt][1]);
                    mma1688(acc[mt][nt], ah0, ah1, ah2, ah3, bl[nt][0], bl[nt][1]);
                    mma1688(acc[mt][nt], al0, al1, al2, al3, bh[nt][0], bh[nt][1]);
                }
            }
        }
    }

#pragma unroll
    for (int nt = 0; nt < 4; nt++) {
        const int n = n0 + wn + nt * 8 + lc * 2;
        const float2 bv = *(const float2*)(bias + n);
#pragma unroll
        for (int mt = 0; mt < 4; mt++) {
            const int m = m0 + wm + mt * 16 + lr;
            float2 o0 = make_float2(acc[mt][nt][0] + bv.x, acc[mt][nt][1] + bv.y);
            float2 o1 = make_float2(acc[mt][nt][2] + bv.x, acc[mt][nt][3] + bv.y);
            *(float2*)(C + (size_t)m * N + n) = o0;
            *(float2*)(C + (size_t)(m + 8) * N + n) = o1;
        }
    }
}

// Fused QKV projection: grid.x covers 1536 output cols (Q:1024 | K:256 | V:256)
__global__ __launch_bounds__(256) void gemm_qkv(
    const float* __restrict__ x,
    const float* __restrict__ Wq, const float* __restrict__ bq,
    const float* __restrict__ Wk, const float* __restrict__ bk,
    const float* __restrict__ Wv, const float* __restrict__ bv,
    float* __restrict__ Q, float* __restrict__ K, float* __restrict__ V)
{
    const int col0 = blockIdx.x * 128;
    const int m0 = blockIdx.y * 128;
    if (col0 < D_MODEL) {
        gemm_tile(x, Wq, bq, Q, D_MODEL, D_MODEL, m0, col0);
    } else if (col0 < D_MODEL + KV_DIM) {
        gemm_tile(x, Wk, bk, K, KV_DIM, D_MODEL, m0, col0 - D_MODEL);
    } else {
        gemm_tile(x, Wv, bv, V, KV_DIM, D_MODEL, m0, col0 - D_MODEL - KV_DIM);
    }
}

__global__ __launch_bounds__(256) void gemm_o(
    const float* __restrict__ A, const float* __restrict__ W,
    const float* __restrict__ bias, float* __restrict__ C)
{
    gemm_tile(A, W, bias, C, D_MODEL, D_MODEL, blockIdx.y * 128, blockIdx.x * 128);
}

// ---------------------------------------------------------------------------
// Causal GQA flash attention, 8x8 micro-tiles.
// CTA: 128 q-rows x (64-key tiles), 128 threads (16x8), frag 8q x 8k.
// ---------------------------------------------------------------------------
#define QS_ST 132
#define KS_ST 68
#define VS_ST 68
#define PS_ST 132
#define ATTN_SMEM ((64 * QS_ST + 64 * KS_ST + 64 * VS_ST + 64 * PS_ST) * 4)

__global__ __launch_bounds__(128) void attn_kernel()
{
    extern __shared__ float sm[];
    float* Qs = sm;                    // [d=64][128+4]  (transposed)
    float* Ks = Qs + 64 * QS_ST;       // [d=64][64+4]   (transposed)
    float* Vs = Ks + 64 * KS_ST;       // [kj=64][64+4]
    float* Ps = Vs + 64 * VS_ST;       // [kj=64][128+4] (P transposed)

    const int tid = threadIdx.x;
    const int tx = tid & 7;            // key-col group
    const int ty = tid >> 3;           // q-row group (0..15)
    const int qt = blockIdx.x;
    const int h  = blockIdx.y;
    const int b  = blockIdx.z;
    const int g  = h >> 2;
    const int tb = b * TSEQ;

    // Load Q tile (128 rows, thread r loads row r, stores transposed).
    {
        const float* qr = g_Q + (size_t)(tb + qt * 128 + tid) * D_MODEL + h * HEAD_DIM;
#pragma unroll
        for (int d4 = 0; d4 < 16; d4++) {
            float4 v = *(const float4*)(qr + d4 * 4);
            Qs[(d4 * 4 + 0) * QS_ST + tid] = v.x;
            Qs[(d4 * 4 + 1) * QS_ST + tid] = v.y;
            Qs[(d4 * 4 + 2) * QS_ST + tid] = v.z;
            Qs[(d4 * 4 + 3) * QS_ST + tid] = v.w;
        }
    }

    float o[8][8];
#pragma unroll
    for (int i = 0; i < 8; i++)
#pragma unroll
        for (int c = 0; c < 8; c++) o[i][c] = 0.0f;
    float m[8], l[8];
#pragma unroll
    for (int i = 0; i < 8; i++) { m[i] = -1e30f; l[i] = 0.0f; }

    const float scale = 0.125f;
    const int nkt = 2 * qt + 2;

    for (int kt = 0; kt < nkt; kt++) {
        __syncthreads();
        // Threads 0-63 load K rows (transposed), 64-127 load V rows.
        if (tid < 64) {
            const float* kr = g_K + (size_t)(tb + kt * 64 + tid) * KV_DIM + g * HEAD_DIM;
#pragma unroll
            for (int d4 = 0; d4 < 16; d4++) {
                float4 v = *(const float4*)(kr + d4 * 4);
                Ks[(d4 * 4 + 0) * KS_ST + tid] = v.x;
                Ks[(d4 * 4 + 1) * KS_ST + tid] = v.y;
                Ks[(d4 * 4 + 2) * KS_ST + tid] = v.z;
                Ks[(d4 * 4 + 3) * KS_ST + tid] = v.w;
            }
        } else {
            const int r = tid - 64;
            const float* vr = g_V + (size_t)(tb + kt * 64 + r) * KV_DIM + g * HEAD_DIM;
#pragma unroll
            for (int d4 = 0; d4 < 16; d4++)
                *(float4*)(Vs + r * VS_ST + d4 * 4) = *(const float4*)(vr + d4 * 4);
        }
        __syncthreads();

        // S = Q @ K^T  (8x8 fragment)
        float s[8][8];
#pragma unroll
        for (int i = 0; i < 8; i++)
#pragma unroll
            for (int j = 0; j < 8; j++) s[i][j] = 0.0f;
#pragma unroll 4
        for (int d = 0; d < 64; d++) {
            float qa[8], ka[8];
            *(float4*)&qa[0] = *(float4*)(Qs + d * QS_ST + ty * 8);
            *(float4*)&qa[4] = *(float4*)(Qs + d * QS_ST + ty * 8 + 4);
            *(float4*)&ka[0] = *(float4*)(Ks + d * KS_ST + tx * 8);
            *(float4*)&ka[4] = *(float4*)(Ks + d * KS_ST + tx * 8 + 4);
#pragma unroll
            for (int i = 0; i < 8; i++)
#pragma unroll
                for (int j = 0; j < 8; j++)
                    s[i][j] = fmaf(qa[i], ka[j], s[i][j]);
        }

        // Scale + causal mask (only the top two key tiles intersect the diagonal).
        if (kt >= 2 * qt) {
#pragma unroll
            for (int i = 0; i < 8; i++) {
                const int qi = qt * 128 + ty * 8 + i;
#pragma unroll
                for (int j = 0; j < 8; j++) {
                    const int kj = kt * 64 + tx * 8 + j;
                    s[i][j] = (kj <= qi) ? s[i][j] * scale : -1e30f;
                }
            }
        } else {
#pragma unroll
            for (int i = 0; i < 8; i++)
#pragma unroll
                for (int j = 0; j < 8; j++) s[i][j] *= scale;
        }

        // Online softmax per row (reduce across 8 tx lanes).
#pragma unroll
        for (int i = 0; i < 8; i++) {
            float rm = s[i][0];
#pragma unroll
            for (int j = 1; j < 8; j++) rm = fmaxf(rm, s[i][j]);
#pragma unroll
            for (int off = 1; off < 8; off <<= 1)
                rm = fmaxf(rm, __shfl_xor_sync(0xffffffffu, rm, off));
            const float mn = fmaxf(m[i], rm);
            const float corr = __expf(m[i] - mn);
            m[i] = mn;
            float rs = 0.0f;
#pragma unroll
            for (int j = 0; j < 8; j++) {
                const float p = __expf(s[i][j] - mn);
                s[i][j] = p;
                rs += p;
            }
#pragma unroll
            for (int off = 1; off < 8; off <<= 1)
                rs += __shfl_xor_sync(0xffffffffu, rs, off);
            l[i] = l[i] * corr + rs;
#pragma unroll
            for (int c = 0; c < 8; c++) o[i][c] *= corr;
        }

        // Store P transposed; rotate j by tx to avoid the stride-132 bank clash.
#pragma unroll
        for (int i = 0; i < 8; i++)
#pragma unroll
            for (int jj = 0; jj < 8; jj++) {
                const int j = (jj + tx) & 7;
                Ps[(tx * 8 + j) * PS_ST + ty * 8 + i] = s[i][j];
            }
        __syncthreads();

        // O += P @ V
#pragma unroll 4
        for (int j = 0; j < 64; j++) {
            float pa[8], va[8];
            *(float4*)&pa[0] = *(float4*)(Ps + j * PS_ST + ty * 8);
            *(float4*)&pa[4] = *(float4*)(Ps + j * PS_ST + ty * 8 + 4);
            *(float4*)&va[0] = *(float4*)(Vs + j * VS_ST + tx * 8);
            *(float4*)&va[4] = *(float4*)(Vs + j * VS_ST + tx * 8 + 4);
#pragma unroll
            for (int i = 0; i < 8; i++)
#pragma unroll
                for (int c = 0; c < 8; c++)
                    o[i][c] = fmaf(pa[i], va[c], o[i][c]);
        }
    }

    // Normalize and write out.
#pragma unroll
    for (int i = 0; i < 8; i++) {
        const float inv = 1.0f / l[i];
        const int row = tb + qt * 128 + ty * 8 + i;
        float* orow = g_O + (size_t)row * D_MODEL + h * HEAD_DIM + tx * 8;
        float4 o0 = make_float4(o[i][0] * inv, o[i][1] * inv, o[i][2] * inv, o[i][3] * inv);
        float4 o1 = make_float4(o[i][4] * inv, o[i][5] * inv, o[i][6] * inv, o[i][7] * inv);
        *(float4*)(orow)     = o0;
        *(float4*)(orow + 4) = o1;
    }
}

// ---------------------------------------------------------------------------
extern "C" void kernel_launch(void* const* d_in, const int* in_sizes, int n_in,
                              void* d_out, int out_size)
{
    const float* x  = (const float*)d_in[0];
    const float* Wq = (const float*)d_in[1];
    const float* bq = (const float*)d_in[2];
    const float* Wk = (const float*)d_in[3];
    const float* bk = (const float*)d_in[4];
    const float* Wv = (const float*)d_in[5];
    const float* bv = (const float*)d_in[6];
    const float* Wo = (const float*)d_in[7];
    const float* bo = (const float*)d_in[8];
    float* out = (float*)d_out;

    float *Qp, *Kp, *Vp, *Op;
    cudaGetSymbolAddress((void**)&Qp, g_Q);
    cudaGetSymbolAddress((void**)&Kp, g_K);
    cudaGetSymbolAddress((void**)&Vp, g_V);
    cudaGetSymbolAddress((void**)&Op, g_O);

    const int gdyn = SM_FLOATS * 4;   // 70656 B
    cudaFuncSetAttribute(gemm_qkv, cudaFuncAttributeMaxDynamicSharedMemorySize, gdyn);
    cudaFuncSetAttribute(gemm_o,   cudaFuncAttributeMaxDynamicSharedMemorySize, gdyn);
    cudaFuncSetAttribute(attn_kernel, cudaFuncAttributeMaxDynamicSharedMemorySize, ATTN_SMEM);

    // Fused QKV projection (one launch, 384 CTAs).
    gemm_qkv<<<dim3((D_MODEL + 2 * KV_DIM) / 128, BT / 128), 256, gdyn>>>(
        x, Wq, bq, Wk, bk, Wv, bv, Qp, Kp, Vp);

    // Causal GQA attention (128-row q tiles).
    attn_kernel<<<dim3(TSEQ / 128, N_HEADS, BATCH), 128, ATTN_SMEM>>>();

    // Output projection.
    gemm_o<<<dim3(D_MODEL / 128, BT / 128), 256, gdyn>>>(Op, Wo, bo, out);
}

// round 6
// speedup vs baseline: 2.2474x; 2.2474x over previous
#include <cuda_runtime.h>
#include <cstdint>

#define D_MODEL 1024
#define KV_DIM 256
#define N_HEADS 16
#define HEAD_DIM 64
#define TSEQ 2048
#define BATCH 2
#define BT (BATCH * TSEQ)

// Scratch (device globals; no allocation anywhere).
__device__ float g_Q[(size_t)BT * D_MODEL];
__device__ float g_K[(size_t)BT * KV_DIM];
__device__ float g_V[(size_t)BT * KV_DIM];
__device__ float g_O[(size_t)BT * D_MODEL];

// ---------------------------------------------------------------------------
// Helpers
// ---------------------------------------------------------------------------
__device__ __forceinline__ float f2tf32(float v) {
    uint32_t u; asm("cvt.rna.tf32.f32 %0, %1;" : "=r"(u) : "f"(v));
    return __uint_as_float(u);
}

__device__ __forceinline__ void mma1688(float* d, float a0, float a1, float a2,
                                        float a3, float b0, float b1) {
    asm volatile(
        "mma.sync.aligned.m16n8k8.row.col.f32.tf32.tf32.f32 "
        "{%0,%1,%2,%3}, {%4,%5,%6,%7}, {%8,%9}, {%0,%1,%2,%3};"
        : "+f"(d[0]), "+f"(d[1]), "+f"(d[2]), "+f"(d[3])
        : "r"(__float_as_uint(a0)), "r"(__float_as_uint(a1)),
          "r"(__float_as_uint(a2)), "r"(__float_as_uint(a3)),
          "r"(__float_as_uint(b0)), "r"(__float_as_uint(b1)));
}

// ---------------------------------------------------------------------------
// 3xTF32 mma.sync GEMM tile (proven): C[128,128] at (m0,n0) = A @ W + bias
// ---------------------------------------------------------------------------
#define AST 36
#define BST 132
#define SM_AH 0
#define SM_AL (128 * AST)
#define SM_BH (2 * 128 * AST)
#define SM_BL (2 * 128 * AST + 32 * BST)
#define SM_FLOATS (2 * 128 * AST + 2 * 32 * BST)

__device__ __forceinline__ void gemm_tile(
    const float* __restrict__ A, const float* __restrict__ W,
    const float* __restrict__ bias, float* __restrict__ C,
    int N, int K, int m0, int n0)
{
    extern __shared__ float s[];

    const int tid = threadIdx.x;
    const int lane = tid & 31;
    const int wid = tid >> 5;
    const int wm = (wid >> 2) * 64;
    const int wn = (wid & 3) * 32;
    const int lr = lane >> 2;
    const int lc = lane & 3;

    const int arow = tid >> 1;
    const int ac0 = (tid & 1) * 16;
    const int brow = tid >> 3;
    const int bc0 = (tid & 7) * 16;

    float acc[4][4][4];
#pragma unroll
    for (int i = 0; i < 4; i++)
#pragma unroll
        for (int j = 0; j < 4; j++)
#pragma unroll
            for (int k = 0; k < 4; k++) acc[i][j][k] = 0.0f;

    const float* Ar = A + (size_t)(m0 + arow) * K;

    for (int kc = 0; kc < K; kc += 32) {
        __syncthreads();
#pragma unroll
        for (int i = 0; i < 4; i++) {
            float4 v = *(const float4*)(Ar + kc + ac0 + i * 4);
            float hx = f2tf32(v.x), hy = f2tf32(v.y),
                  hz = f2tf32(v.z), hw = f2tf32(v.w);
            const int o = arow * AST + ac0 + i * 4;
            s[SM_AH + o + 0] = hx; s[SM_AL + o + 0] = f2tf32(v.x - hx);
            s[SM_AH + o + 1] = hy; s[SM_AL + o + 1] = f2tf32(v.y - hy);
            s[SM_AH + o + 2] = hz; s[SM_AL + o + 2] = f2tf32(v.z - hz);
            s[SM_AH + o + 3] = hw; s[SM_AL + o + 3] = f2tf32(v.w - hw);
        }
#pragma unroll
        for (int i = 0; i < 4; i++) {
            float4 v = *(const float4*)(W + (size_t)(kc + brow) * N + n0 + bc0 + i * 4);
            float hx = f2tf32(v.x), hy = f2tf32(v.y),
                  hz = f2tf32(v.z), hw = f2tf32(v.w);
            const int o = brow * BST + bc0 + i * 4;
            s[SM_BH + o + 0] = hx; s[SM_BL + o + 0] = f2tf32(v.x - hx);
            s[SM_BH + o + 1] = hy; s[SM_BL + o + 1] = f2tf32(v.y - hy);
            s[SM_BH + o + 2] = hz; s[SM_BL + o + 2] = f2tf32(v.z - hz);
            s[SM_BH + o + 3] = hw; s[SM_BL + o + 3] = f2tf32(v.w - hw);
        }
        __syncthreads();

#pragma unroll
        for (int kk = 0; kk < 4; kk++) {
            const int kb = kk * 8;
            float bh[4][2], bl[4][2];
#pragma unroll
            for (int nt = 0; nt < 4; nt++) {
                const int n = wn + nt * 8 + lr;
                bh[nt][0] = s[SM_BH + (kb + lc) * BST + n];
                bh[nt][1] = s[SM_BH + (kb + 4 + lc) * BST + n];
                bl[nt][0] = s[SM_BL + (kb + lc) * BST + n];
                bl[nt][1] = s[SM_BL + (kb + 4 + lc) * BST + n];
            }
#pragma unroll
            for (int mt = 0; mt < 4; mt++) {
                const int m = wm + mt * 16 + lr;
                float ah0 = s[SM_AH + m * AST + kb + lc];
                float ah1 = s[SM_AH + (m + 8) * AST + kb + lc];
                float ah2 = s[SM_AH + m * AST + kb + 4 + lc];
                float ah3 = s[SM_AH + (m + 8) * AST + kb + 4 + lc];
                float al0 = s[SM_AL + m * AST + kb + lc];
                float al1 = s[SM_AL + (m + 8) * AST + kb + lc];
                float al2 = s[SM_AL + m * AST + kb + 4 + lc];
                float al3 = s[SM_AL + (m + 8) * AST + kb + 4 + lc];
#pragma unroll
                for (int nt = 0; nt < 4; nt++) {
                    mma1688(acc[mt][nt], ah0, ah1, ah2, ah3, bh[nt][0], bh[nt][1]);
                    mma1688(acc[mt][nt], ah0, ah1, ah2, ah3, bl[nt][0], bl[nt][1]);
                    mma1688(acc[mt][nt], al0, al1, al2, al3, bh[nt][0], bh[nt][1]);
                }
            }
        }
    }

#pragma unroll
    for (int nt = 0; nt < 4; nt++) {
        const int n = n0 + wn + nt * 8 + lc * 2;
        const float2 bv = *(const float2*)(bias + n);
#pragma unroll
        for (int mt = 0; mt < 4; mt++) {
            const int m = m0 + wm + mt * 16 + lr;
            float2 o0 = make_float2(acc[mt][nt][0] + bv.x, acc[mt][nt][1] + bv.y);
            float2 o1 = make_float2(acc[mt][nt][2] + bv.x, acc[mt][nt][3] + bv.y);
            *(float2*)(C + (size_t)m * N + n) = o0;
            *(float2*)(C + (size_t)(m + 8) * N + n) = o1;
        }
    }
}

// Fused QKV projection: grid.x covers 1536 output cols (Q:1024 | K:256 | V:256)
__global__ __launch_bounds__(256) void gemm_qkv(
    const float* __restrict__ x,
    const float* __restrict__ Wq, const float* __restrict__ bq,
    const float* __restrict__ Wk, const float* __restrict__ bk,
    const float* __restrict__ Wv, const float* __restrict__ bv,
    float* __restrict__ Q, float* __restrict__ K, float* __restrict__ V)
{
    const int col0 = blockIdx.x * 128;
    const int m0 = blockIdx.y * 128;
    if (col0 < D_MODEL) {
        gemm_tile(x, Wq, bq, Q, D_MODEL, D_MODEL, m0, col0);
    } else if (col0 < D_MODEL + KV_DIM) {
        gemm_tile(x, Wk, bk, K, KV_DIM, D_MODEL, m0, col0 - D_MODEL);
    } else {
        gemm_tile(x, Wv, bv, V, KV_DIM, D_MODEL, m0, col0 - D_MODEL - KV_DIM);
    }
}

__global__ __launch_bounds__(256) void gemm_o(
    const float* __restrict__ A, const float* __restrict__ W,
    const float* __restrict__ bias, float* __restrict__ C)
{
    gemm_tile(A, W, bias, C, D_MODEL, D_MODEL, blockIdx.y * 128, blockIdx.x * 128);
}

// ---------------------------------------------------------------------------
// Causal GQA flash attention on mma.sync (single tf32).
// CTA: 128 q-rows, 64-key tiles, 256 threads = 8 warps; each warp owns one
// 16-row band x full 64 keys / 64 d. Softmax in C-fragment registers.
// P round-trips through smem warp-locally (no block barrier).
// ---------------------------------------------------------------------------
#define AT_ST 68
#define ATTN_SMEM (384 * AT_ST * 4)   // Qs(128) + Ks(64) + Vt(64) + Ps(128) rows

__global__ __launch_bounds__(256) void attn_mma()
{
    extern __shared__ float sm[];
    float* Qs = sm;                    // [128][AT_ST]  rows q,  cols d (pre-scaled)
    float* Ks = Qs + 128 * AT_ST;      // [64][AT_ST]   rows key, cols d
    float* Vt = Ks + 64 * AT_ST;       // [64][AT_ST]   rows d,  cols key (transposed)
    float* Ps = Vt + 64 * AT_ST;       // [128][AT_ST]  rows q,  cols key

    const int tid = threadIdx.x;
    const int lane = tid & 31;
    const int w = tid >> 5;
    const int lr = lane >> 2;
    const int lc = lane & 3;
    const int qt = blockIdx.x, h = blockIdx.y, b = blockIdx.z;
    const int g = h >> 2;
    const int tb = b * TSEQ;
    const float scale = 0.125f;

    // Stage Q (scaled + tf32-rounded).
    {
        const int r = tid >> 1, c0 = (tid & 1) * 32;
        const float* qr = g_Q + (size_t)(tb + qt * 128 + r) * D_MODEL + h * HEAD_DIM + c0;
        float* dst = Qs + r * AT_ST + c0;
#pragma unroll
        for (int i = 0; i < 8; i++) {
            float4 v = *(const float4*)(qr + i * 4);
            v.x = f2tf32(v.x * scale); v.y = f2tf32(v.y * scale);
            v.z = f2tf32(v.z * scale); v.w = f2tf32(v.w * scale);
            *(float4*)(dst + i * 4) = v;
        }
    }

    float oacc[8][4];
#pragma unroll
    for (int nt = 0; nt < 8; nt++)
#pragma unroll
        for (int j = 0; j < 4; j++) oacc[nt][j] = 0.0f;
    float m0 = -1e30f, m1 = -1e30f, l0 = 0.0f, l1 = 0.0f;

    const int r0 = w * 16 + lr;          // local q row (first of pair)
    const int qi0 = qt * 128 + r0;
    const int qi1 = qi0 + 8;

    const int nkt = 2 * qt + 2;
    for (int kt = 0; kt < nkt; kt++) {
        __syncthreads();
        // Stage K (row-major) and V (transposed), tf32-rounded.
        {
            const int r = tid >> 2, c0 = (tid & 3) * 16;
            const float* kr = g_K + (size_t)(tb + kt * 64 + r) * KV_DIM + g * HEAD_DIM + c0;
            float* kd = Ks + r * AT_ST + c0;
#pragma unroll
            for (int i = 0; i < 4; i++) {
                float4 v = *(const float4*)(kr + i * 4);
                v.x = f2tf32(v.x); v.y = f2tf32(v.y);
                v.z = f2tf32(v.z); v.w = f2tf32(v.w);
                *(float4*)(kd + i * 4) = v;
            }
            const float* vr = g_V + (size_t)(tb + kt * 64 + r) * KV_DIM + g * HEAD_DIM + c0;
#pragma unroll
            for (int i = 0; i < 4; i++) {
                float4 v = *(const float4*)(vr + i * 4);
                Vt[(c0 + i * 4 + 0) * AT_ST + r] = f2tf32(v.x);
                Vt[(c0 + i * 4 + 1) * AT_ST + r] = f2tf32(v.y);
                Vt[(c0 + i * 4 + 2) * AT_ST + r] = f2tf32(v.z);
                Vt[(c0 + i * 4 + 3) * AT_ST + r] = f2tf32(v.w);
            }
        }
        __syncthreads();

        // S = Q @ K^T  (8 n-tiles of 8 keys)
        float sa[8][4];
#pragma unroll
        for (int nt = 0; nt < 8; nt++)
#pragma unroll
            for (int j = 0; j < 4; j++) sa[nt][j] = 0.0f;
#pragma unroll
        for (int kb = 0; kb < 64; kb += 8) {
            const float* q0 = Qs + r0 * AT_ST + kb + lc;
            const float a0 = q0[0];
            const float a1 = q0[8 * AT_ST];
            const float a2 = q0[4];
            const float a3 = q0[8 * AT_ST + 4];
#pragma unroll
            for (int nt = 0; nt < 8; nt++) {
                const float* kk = Ks + (nt * 8 + lr) * AT_ST + kb + lc;
                mma1688(sa[nt], a0, a1, a2, a3, kk[0], kk[4]);
            }
        }

        // Causal mask (only the two diagonal-adjacent key tiles need it).
        if (kt >= 2 * qt) {
#pragma unroll
            for (int nt = 0; nt < 8; nt++) {
                const int kj = kt * 64 + nt * 8 + 2 * lc;
                if (kj > qi0)     sa[nt][0] = -1e30f;
                if (kj + 1 > qi0) sa[nt][1] = -1e30f;
                if (kj > qi1)     sa[nt][2] = -1e30f;
                if (kj + 1 > qi1) sa[nt][3] = -1e30f;
            }
        }

        // Online softmax: rows r0 (frag 0,1) and r0+8 (frag 2,3); quad-reduce.
        float mx0 = sa[0][0], mx1 = sa[0][2];
#pragma unroll
        for (int nt = 0; nt < 8; nt++) {
            mx0 = fmaxf(mx0, fmaxf(sa[nt][0], sa[nt][1]));
            mx1 = fmaxf(mx1, fmaxf(sa[nt][2], sa[nt][3]));
        }
        mx0 = fmaxf(mx0, __shfl_xor_sync(0xffffffffu, mx0, 1));
        mx0 = fmaxf(mx0, __shfl_xor_sync(0xffffffffu, mx0, 2));
        mx1 = fmaxf(mx1, __shfl_xor_sync(0xffffffffu, mx1, 1));
        mx1 = fmaxf(mx1, __shfl_xor_sync(0xffffffffu, mx1, 2));
        const float nm0 = fmaxf(m0, mx0), nm1 = fmaxf(m1, mx1);
        const float cf0 = __expf(m0 - nm0), cf1 = __expf(m1 - nm1);
        m0 = nm0; m1 = nm1;
        float rs0 = 0.0f, rs1 = 0.0f;
#pragma unroll
        for (int nt = 0; nt < 8; nt++) {
            float p0 = __expf(sa[nt][0] - nm0);
            float p1 = __expf(sa[nt][1] - nm0);
            float p2 = __expf(sa[nt][2] - nm1);
            float p3 = __expf(sa[nt][3] - nm1);
            rs0 += p0 + p1; rs1 += p2 + p3;
            sa[nt][0] = f2tf32(p0); sa[nt][1] = f2tf32(p1);
            sa[nt][2] = f2tf32(p2); sa[nt][3] = f2tf32(p3);
        }
        rs0 += __shfl_xor_sync(0xffffffffu, rs0, 1);
        rs0 += __shfl_xor_sync(0xffffffffu, rs0, 2);
        rs1 += __shfl_xor_sync(0xffffffffu, rs1, 1);
        rs1 += __shfl_xor_sync(0xffffffffu, rs1, 2);
        l0 = l0 * cf0 + rs0;
        l1 = l1 * cf1 + rs1;
#pragma unroll
        for (int nt = 0; nt < 8; nt++) {
            oacc[nt][0] *= cf0; oacc[nt][1] *= cf0;
            oacc[nt][2] *= cf1; oacc[nt][3] *= cf1;
        }

        // P -> smem (warp-local rows only), then O += P @ V.
#pragma unroll
        for (int nt = 0; nt < 8; nt++) {
            *(float2*)(Ps + r0 * AT_ST + nt * 8 + 2 * lc) =
                make_float2(sa[nt][0], sa[nt][1]);
            *(float2*)(Ps + (r0 + 8) * AT_ST + nt * 8 + 2 * lc) =
                make_float2(sa[nt][2], sa[nt][3]);
        }
        __syncwarp();

#pragma unroll
        for (int kb = 0; kb < 64; kb += 8) {
            const float* pr = Ps + r0 * AT_ST + kb + lc;
            const float a0 = pr[0];
            const float a1 = pr[8 * AT_ST];
            const float a2 = pr[4];
            const float a3 = pr[8 * AT_ST + 4];
#pragma unroll
            for (int nt = 0; nt < 8; nt++) {
                const float* vv = Vt + (nt * 8 + lr) * AT_ST + kb + lc;
                mma1688(oacc[nt], a0, a1, a2, a3, vv[0], vv[4]);
            }
        }
        __syncwarp();   // Ps reads done before next iteration overwrites
    }

    // Normalize and write out.
    const float inv0 = 1.0f / l0, inv1 = 1.0f / l1;
    float* orow0 = g_O + (size_t)(tb + qt * 128 + r0) * D_MODEL + h * HEAD_DIM;
    float* orow1 = orow0 + 8 * D_MODEL;
#pragma unroll
    for (int nt = 0; nt < 8; nt++) {
        *(float2*)(orow0 + nt * 8 + 2 * lc) =
            make_float2(oacc[nt][0] * inv0, oacc[nt][1] * inv0);
        *(float2*)(orow1 + nt * 8 + 2 * lc) =
            make_float2(oacc[nt][2] * inv1, oacc[nt][3] * inv1);
    }
}

// ---------------------------------------------------------------------------
extern "C" void kernel_launch(void* const* d_in, const int* in_sizes, int n_in,
                              void* d_out, int out_size)
{
    const float* x  = (const float*)d_in[0];
    const float* Wq = (const float*)d_in[1];
    const float* bq = (const float*)d_in[2];
    const float* Wk = (const float*)d_in[3];
    const float* bk = (const float*)d_in[4];
    const float* Wv = (const float*)d_in[5];
    const float* bv = (const float*)d_in[6];
    const float* Wo = (const float*)d_in[7];
    const float* bo = (const float*)d_in[8];
    float* out = (float*)d_out;

    float *Qp, *Kp, *Vp, *Op;
    cudaGetSymbolAddress((void**)&Qp, g_Q);
    cudaGetSymbolAddress((void**)&Kp, g_K);
    cudaGetSymbolAddress((void**)&Vp, g_V);
    cudaGetSymbolAddress((void**)&Op, g_O);

    const int gdyn = SM_FLOATS * 4;   // 70656 B
    cudaFuncSetAttribute(gemm_qkv, cudaFuncAttributeMaxDynamicSharedMemorySize, gdyn);
    cudaFuncSetAttribute(gemm_o,   cudaFuncAttributeMaxDynamicSharedMemorySize, gdyn);
    cudaFuncSetAttribute(attn_mma, cudaFuncAttributeMaxDynamicSharedMemorySize, ATTN_SMEM);

    // Fused QKV projection (one launch, 384 CTAs).
    gemm_qkv<<<dim3((D_MODEL + 2 * KV_DIM) / 128, BT / 128), 256, gdyn>>>(
        x, Wq, bq, Wk, bk, Wv, bv, Qp, Kp, Vp);

    // Causal GQA attention on tensor cores (128-row q tiles).
    attn_mma<<<dim3(TSEQ / 128, N_HEADS, BATCH), 256, ATTN_SMEM>>>();

    // Output projection.
    gemm_o<<<dim3(D_MODEL / 128, BT / 128), 256, gdyn>>>(Op, Wo, bo, out);
}

// round 7
// speedup vs baseline: 2.8392x; 1.2634x over previous
#include <cuda_runtime.h>
#include <cuda_bf16.h>
#include <cstdint>

#define D_MODEL 1024
#define KV_DIM 256
#define N_HEADS 16
#define HEAD_DIM 64
#define TSEQ 2048
#define BATCH 2
#define BT (BATCH * TSEQ)

// Scratch (device globals; no allocation anywhere).
__device__ float g_Q[(size_t)BT * D_MODEL];
__device__ float g_K[(size_t)BT * KV_DIM];
__device__ float g_V[(size_t)BT * KV_DIM];
__device__ float g_O[(size_t)BT * D_MODEL];

// ---------------------------------------------------------------------------
// Helpers
// ---------------------------------------------------------------------------
__device__ __forceinline__ float f2tf32(float v) {
    uint32_t u; asm("cvt.rna.tf32.f32 %0, %1;" : "=r"(u) : "f"(v));
    return __uint_as_float(u);
}

__device__ __forceinline__ void mma1688(float* d, float a0, float a1, float a2,
                                        float a3, float b0, float b1) {
    asm volatile(
        "mma.sync.aligned.m16n8k8.row.col.f32.tf32.tf32.f32 "
        "{%0,%1,%2,%3}, {%4,%5,%6,%7}, {%8,%9}, {%0,%1,%2,%3};"
        : "+f"(d[0]), "+f"(d[1]), "+f"(d[2]), "+f"(d[3])
        : "r"(__float_as_uint(a0)), "r"(__float_as_uint(a1)),
          "r"(__float_as_uint(a2)), "r"(__float_as_uint(a3)),
          "r"(__float_as_uint(b0)), "r"(__float_as_uint(b1)));
}

__device__ __forceinline__ void mma16816(float* d, uint32_t a0, uint32_t a1,
                                         uint32_t a2, uint32_t a3,
                                         uint32_t b0, uint32_t b1) {
    asm volatile(
        "mma.sync.aligned.m16n8k16.row.col.f32.bf16.bf16.f32 "
        "{%0,%1,%2,%3}, {%4,%5,%6,%7}, {%8,%9}, {%0,%1,%2,%3};"
        : "+f"(d[0]), "+f"(d[1]), "+f"(d[2]), "+f"(d[3])
        : "r"(a0), "r"(a1), "r"(a2), "r"(a3), "r"(b0), "r"(b1));
}

__device__ __forceinline__ uint32_t packbf(__nv_bfloat16 a, __nv_bfloat16 b) {
    __nv_bfloat162 t(a, b);   // a -> low 16 bits
    return *reinterpret_cast<uint32_t*>(&t);
}

// ---------------------------------------------------------------------------
// 2-term bf16-split mma.sync GEMM tile: C[128,128] at (m0,n0) = A @ W + bias
// 256 threads (8 warps, 2x4), 64x32 warp tile, K-chunk 32 (2 k16 steps).
// x = x0 + x1 (bf16 split); D = x0 w0 + x0 w1 + x1 w0  (error ~2^-16).
// smem layout (u32 units, stride 20 -> 20r+lc mod 32 conflict-free):
//   AH [128][20], AL [128][20], BH [128 n][20], BL [128 n][20]
// ---------------------------------------------------------------------------
#define GROW 20
#define G_AH 0
#define G_AL (128 * GROW)
#define G_BH (2 * 128 * GROW)
#define G_BL (3 * 128 * GROW)
#define G_U32 (4 * 128 * GROW)
#define GEMM_SMEM (G_U32 * 4)   // 40960 B

__device__ __forceinline__ void gemm_tile(
    const float* __restrict__ A, const float* __restrict__ W,
    const float* __restrict__ bias, float* __restrict__ C,
    int N, int K, int m0, int n0)
{
    extern __shared__ uint32_t su[];

    const int tid = threadIdx.x;
    const int lane = tid & 31;
    const int wid = tid >> 5;
    const int wm = (wid >> 2) * 64;
    const int wn = (wid & 3) * 32;
    const int lr = lane >> 2;
    const int lc = lane & 3;

    // A staging: row = tid>>1, k-half = (tid&1)*16
    const int arow = tid >> 1;
    const int ahalf = (tid & 1) * 16;
    // B staging: n-quad = (tid&31)*4, k-quad = (tid>>5)*4
    const int bn0 = (tid & 31) * 4;
    const int bk0 = (tid >> 5) * 4;

    float acc[4][4][4];
#pragma unroll
    for (int i = 0; i < 4; i++)
#pragma unroll
        for (int j = 0; j < 4; j++)
#pragma unroll
            for (int k = 0; k < 4; k++) acc[i][j][k] = 0.0f;

    const float* Ar = A + (size_t)(m0 + arow) * K + ahalf;

    for (int kc = 0; kc < K; kc += 32) {
        __syncthreads();
        // ---- Stage A[128][32] -> bf16 hi/lo pairs ----
#pragma unroll
        for (int i = 0; i < 4; i++) {
            float4 v = *(const float4*)(Ar + kc + i * 4);
            __nv_bfloat16 hx = __float2bfloat16_rn(v.x);
            __nv_bfloat16 hy = __float2bfloat16_rn(v.y);
            __nv_bfloat16 hz = __float2bfloat16_rn(v.z);
            __nv_bfloat16 hw = __float2bfloat16_rn(v.w);
            uint32_t h01 = packbf(hx, hy), h23 = packbf(hz, hw);
            uint32_t l01 = packbf(__float2bfloat16_rn(v.x - __bfloat162float(hx)),
                                  __float2bfloat16_rn(v.y - __bfloat162float(hy)));
            uint32_t l23 = packbf(__float2bfloat16_rn(v.z - __bfloat162float(hz)),
                                  __float2bfloat16_rn(v.w - __bfloat162float(hw)));
            const int o = arow * GROW + (ahalf >> 1) + i * 2;
            *(uint2*)&su[G_AH + o] = make_uint2(h01, h23);
            *(uint2*)&su[G_AL + o] = make_uint2(l01, l23);
        }
        // ---- Stage B[32][128] transposed -> Bt[n][kpair] bf16 hi/lo ----
        {
            float r[4][4];
#pragma unroll
            for (int dk = 0; dk < 4; dk++)
                *(float4*)r[dk] =
                    *(const float4*)(W + (size_t)(kc + bk0 + dk) * N + n0 + bn0);
#pragma unroll
            for (int j = 0; j < 4; j++) {
                __nv_bfloat16 h0 = __float2bfloat16_rn(r[0][j]);
                __nv_bfloat16 h1 = __float2bfloat16_rn(r[1][j]);
                __nv_bfloat16 h2 = __float2bfloat16_rn(r[2][j]);
                __nv_bfloat16 h3 = __float2bfloat16_rn(r[3][j]);
                uint32_t hh0 = packbf(h0, h1), hh1 = packbf(h2, h3);
                uint32_t ll0 = packbf(__float2bfloat16_rn(r[0][j] - __bfloat162float(h0)),
                                      __float2bfloat16_rn(r[1][j] - __bfloat162float(h1)));
                uint32_t ll1 = packbf(__float2bfloat16_rn(r[2][j] - __bfloat162float(h2)),
                                      __float2bfloat16_rn(r[3][j] - __bfloat162float(h3)));
                const int o = (bn0 + j) * GROW + (bk0 >> 1);
                *(uint2*)&su[G_BH + o] = make_uint2(hh0, hh1);
                *(uint2*)&su[G_BL + o] = make_uint2(ll0, ll1);
            }
        }
        __syncthreads();

        // ---- Mainloop: 2 k16 steps ----
#pragma unroll
        for (int ss = 0; ss < 2; ss++) {
            const int kp = ss * 8 + lc;
            uint32_t bh[4][2], bl[4][2];
#pragma unroll
            for (int nt = 0; nt < 4; nt++) {
                const int n = wn + nt * 8 + lr;
                bh[nt][0] = su[G_BH + n * GROW + kp];
                bh[nt][1] = su[G_BH + n * GROW + kp + 4];
                bl[nt][0] = su[G_BL + n * GROW + kp];
                bl[nt][1] = su[G_BL + n * GROW + kp + 4];
            }
#pragma unroll
            for (int mt = 0; mt < 4; mt++) {
                const int m = wm + mt * 16 + lr;
                uint32_t ah0 = su[G_AH + m * GROW + kp];
                uint32_t ah1 = su[G_AH + (m + 8) * GROW + kp];
                uint32_t ah2 = su[G_AH + m * GROW + kp + 4];
                uint32_t ah3 = su[G_AH + (m + 8) * GROW + kp + 4];
                uint32_t al0 = su[G_AL + m * GROW + kp];
                uint32_t al1 = su[G_AL + (m + 8) * GROW + kp];
                uint32_t al2 = su[G_AL + m * GROW + kp + 4];
                uint32_t al3 = su[G_AL + (m + 8) * GROW + kp + 4];
#pragma unroll
                for (int nt = 0; nt < 4; nt++) {
                    mma16816(acc[mt][nt], ah0, ah1, ah2, ah3, bh[nt][0], bh[nt][1]);
                    mma16816(acc[mt][nt], ah0, ah1, ah2, ah3, bl[nt][0], bl[nt][1]);
                    mma16816(acc[mt][nt], al0, al1, al2, al3, bh[nt][0], bh[nt][1]);
                }
            }
        }
    }

#pragma unroll
    for (int nt = 0; nt < 4; nt++) {
        const int n = n0 + wn + nt * 8 + lc * 2;
        const float2 bv = *(const float2*)(bias + n);
#pragma unroll
        for (int mt = 0; mt < 4; mt++) {
            const int m = m0 + wm + mt * 16 + lr;
            float2 o0 = make_float2(acc[mt][nt][0] + bv.x, acc[mt][nt][1] + bv.y);
            float2 o1 = make_float2(acc[mt][nt][2] + bv.x, acc[mt][nt][3] + bv.y);
            *(float2*)(C + (size_t)m * N + n) = o0;
            *(float2*)(C + (size_t)(m + 8) * N + n) = o1;
        }
    }
}

// Fused QKV projection: grid.x covers 1536 output cols (Q:1024 | K:256 | V:256)
__global__ __launch_bounds__(256) void gemm_qkv(
    const float* __restrict__ x,
    const float* __restrict__ Wq, const float* __restrict__ bq,
    const float* __restrict__ Wk, const float* __restrict__ bk,
    const float* __restrict__ Wv, const float* __restrict__ bv,
    float* __restrict__ Q, float* __restrict__ K, float* __restrict__ V)
{
    const int col0 = blockIdx.x * 128;
    const int m0 = blockIdx.y * 128;
    if (col0 < D_MODEL) {
        gemm_tile(x, Wq, bq, Q, D_MODEL, D_MODEL, m0, col0);
    } else if (col0 < D_MODEL + KV_DIM) {
        gemm_tile(x, Wk, bk, K, KV_DIM, D_MODEL, m0, col0 - D_MODEL);
    } else {
        gemm_tile(x, Wv, bv, V, KV_DIM, D_MODEL, m0, col0 - D_MODEL - KV_DIM);
    }
}

__global__ __launch_bounds__(256) void gemm_o(
    const float* __restrict__ A, const float* __restrict__ W,
    const float* __restrict__ bias, float* __restrict__ C)
{
    gemm_tile(A, W, bias, C, D_MODEL, D_MODEL, blockIdx.y * 128, blockIdx.x * 128);
}

// ---------------------------------------------------------------------------
// Causal GQA flash attention on mma.sync (single tf32). Proven in R6.
// ---------------------------------------------------------------------------
#define AT_ST 68
#define ATTN_SMEM (384 * AT_ST * 4)

__global__ __launch_bounds__(256) void attn_mma()
{
    extern __shared__ float sm[];
    float* Qs = sm;
    float* Ks = Qs + 128 * AT_ST;
    float* Vt = Ks + 64 * AT_ST;
    float* Ps = Vt + 64 * AT_ST;

    const int tid = threadIdx.x;
    const int lane = tid & 31;
    const int w = tid >> 5;
    const int lr = lane >> 2;
    const int lc = lane & 3;
    const int qt = blockIdx.x, h = blockIdx.y, b = blockIdx.z;
    const int g = h >> 2;
    const int tb = b * TSEQ;
    const float scale = 0.125f;

    {
        const int r = tid >> 1, c0 = (tid & 1) * 32;
        const float* qr = g_Q + (size_t)(tb + qt * 128 + r) * D_MODEL + h * HEAD_DIM + c0;
        float* dst = Qs + r * AT_ST + c0;
#pragma unroll
        for (int i = 0; i < 8; i++) {
            float4 v = *(const float4*)(qr + i * 4);
            v.x = f2tf32(v.x * scale); v.y = f2tf32(v.y * scale);
            v.z = f2tf32(v.z * scale); v.w = f2tf32(v.w * scale);
            *(float4*)(dst + i * 4) = v;
        }
    }

    float oacc[8][4];
#pragma unroll
    for (int nt = 0; nt < 8; nt++)
#pragma unroll
        for (int j = 0; j < 4; j++) oacc[nt][j] = 0.0f;
    float m0 = -1e30f, m1 = -1e30f, l0 = 0.0f, l1 = 0.0f;

    const int r0 = w * 16 + lr;
    const int qi0 = qt * 128 + r0;
    const int qi1 = qi0 + 8;

    const int nkt = 2 * qt + 2;
    for (int kt = 0; kt < nkt; kt++) {
        __syncthreads();
        {
            const int r = tid >> 2, c0 = (tid & 3) * 16;
            const float* kr = g_K + (size_t)(tb + kt * 64 + r) * KV_DIM + g * HEAD_DIM + c0;
            float* kd = Ks + r * AT_ST + c0;
#pragma unroll
            for (int i = 0; i < 4; i++) {
                float4 v = *(const float4*)(kr + i * 4);
                v.x = f2tf32(v.x); v.y = f2tf32(v.y);
                v.z = f2tf32(v.z); v.w = f2tf32(v.w);
                *(float4*)(kd + i * 4) = v;
            }
            const float* vr = g_V + (size_t)(tb + kt * 64 + r) * KV_DIM + g * HEAD_DIM + c0;
#pragma unroll
            for (int i = 0; i < 4; i++) {
                float4 v = *(const float4*)(vr + i * 4);
                Vt[(c0 + i * 4 + 0) * AT_ST + r] = f2tf32(v.x);
                Vt[(c0 + i * 4 + 1) * AT_ST + r] = f2tf32(v.y);
                Vt[(c0 + i * 4 + 2) * AT_ST + r] = f2tf32(v.z);
                Vt[(c0 + i * 4 + 3) * AT_ST + r] = f2tf32(v.w);
            }
        }
        __syncthreads();

        float sa[8][4];
#pragma unroll
        for (int nt = 0; nt < 8; nt++)
#pragma unroll
            for (int j = 0; j < 4; j++) sa[nt][j] = 0.0f;
#pragma unroll
        for (int kb = 0; kb < 64; kb += 8) {
            const float* q0 = Qs + r0 * AT_ST + kb + lc;
            const float a0 = q0[0];
            const float a1 = q0[8 * AT_ST];
            const float a2 = q0[4];
            const float a3 = q0[8 * AT_ST + 4];
#pragma unroll
            for (int nt = 0; nt < 8; nt++) {
                const float* kk = Ks + (nt * 8 + lr) * AT_ST + kb + lc;
                mma1688(sa[nt], a0, a1, a2, a3, kk[0], kk[4]);
            }
        }

        if (kt >= 2 * qt) {
#pragma unroll
            for (int nt = 0; nt < 8; nt++) {
                const int kj = kt * 64 + nt * 8 + 2 * lc;
                if (kj > qi0)     sa[nt][0] = -1e30f;
                if (kj + 1 > qi0) sa[nt][1] = -1e30f;
                if (kj > qi1)     sa[nt][2] = -1e30f;
                if (kj + 1 > qi1) sa[nt][3] = -1e30f;
            }
        }

        float mx0 = sa[0][0], mx1 = sa[0][2];
#pragma unroll
        for (int nt = 0; nt < 8; nt++) {
            mx0 = fmaxf(mx0, fmaxf(sa[nt][0], sa[nt][1]));
            mx1 = fmaxf(mx1, fmaxf(sa[nt][2], sa[nt][3]));
        }
        mx0 = fmaxf(mx0, __shfl_xor_sync(0xffffffffu, mx0, 1));
        mx0 = fmaxf(mx0, __shfl_xor_sync(0xffffffffu, mx0, 2));
        mx1 = fmaxf(mx1, __shfl_xor_sync(0xffffffffu, mx1, 1));
        mx1 = fmaxf(mx1, __shfl_xor_sync(0xffffffffu, mx1, 2));
        const float nm0 = fmaxf(m0, mx0), nm1 = fmaxf(m1, mx1);
        const float cf0 = __expf(m0 - nm0), cf1 = __expf(m1 - nm1);
        m0 = nm0; m1 = nm1;
        float rs0 = 0.0f, rs1 = 0.0f;
#pragma unroll
        for (int nt = 0; nt < 8; nt++) {
            float p0 = __expf(sa[nt][0] - nm0);
            float p1 = __expf(sa[nt][1] - nm0);
            float p2 = __expf(sa[nt][2] - nm1);
            float p3 = __expf(sa[nt][3] - nm1);
            rs0 += p0 + p1; rs1 += p2 + p3;
            sa[nt][0] = f2tf32(p0); sa[nt][1] = f2tf32(p1);
            sa[nt][2] = f2tf32(p2); sa[nt][3] = f2tf32(p3);
        }
        rs0 += __shfl_xor_sync(0xffffffffu, rs0, 1);
        rs0 += __shfl_xor_sync(0xffffffffu, rs0, 2);
        rs1 += __shfl_xor_sync(0xffffffffu, rs1, 1);
        rs1 += __shfl_xor_sync(0xffffffffu, rs1, 2);
        l0 = l0 * cf0 + rs0;
        l1 = l1 * cf1 + rs1;
#pragma unroll
        for (int nt = 0; nt < 8; nt++) {
            oacc[nt][0] *= cf0; oacc[nt][1] *= cf0;
            oacc[nt][2] *= cf1; oacc[nt][3] *= cf1;
        }

#pragma unroll
        for (int nt = 0; nt < 8; nt++) {
            *(float2*)(Ps + r0 * AT_ST + nt * 8 + 2 * lc) =
                make_float2(sa[nt][0], sa[nt][1]);
            *(float2*)(Ps + (r0 + 8) * AT_ST + nt * 8 + 2 * lc) =
                make_float2(sa[nt][2], sa[nt][3]);
        }
        __syncwarp();

#pragma unroll
        for (int kb = 0; kb < 64; kb += 8) {
            const float* pr = Ps + r0 * AT_ST + kb + lc;
            const float a0 = pr[0];
            const float a1 = pr[8 * AT_ST];
            const float a2 = pr[4];
            const float a3 = pr[8 * AT_ST + 4];
#pragma unroll
            for (int nt = 0; nt < 8; nt++) {
                const float* vv = Vt + (nt * 8 + lr) * AT_ST + kb + lc;
                mma1688(oacc[nt], a0, a1, a2, a3, vv[0], vv[4]);
            }
        }
        __syncwarp();
    }

    const float inv0 = 1.0f / l0, inv1 = 1.0f / l1;
    float* orow0 = g_O + (size_t)(tb + qt * 128 + r0) * D_MODEL + h * HEAD_DIM;
    float* orow1 = orow0 + 8 * D_MODEL;
#pragma unroll
    for (int nt = 0; nt < 8; nt++) {
        *(float2*)(orow0 + nt * 8 + 2 * lc) =
            make_float2(oacc[nt][0] * inv0, oacc[nt][1] * inv0);
        *(float2*)(orow1 + nt * 8 + 2 * lc) =
            make_float2(oacc[nt][2] * inv1, oacc[nt][3] * inv1);
    }
}

// ---------------------------------------------------------------------------
extern "C" void kernel_launch(void* const* d_in, const int* in_sizes, int n_in,
                              void* d_out, int out_size)
{
    const float* x  = (const float*)d_in[0];
    const float* Wq = (const float*)d_in[1];
    const float* bq = (const float*)d_in[2];
    const float* Wk = (const float*)d_in[3];
    const float* bk = (const float*)d_in[4];
    const float* Wv = (const float*)d_in[5];
    const float* bv = (const float*)d_in[6];
    const float* Wo = (const float*)d_in[7];
    const float* bo = (const float*)d_in[8];
    float* out = (float*)d_out;

    float *Qp, *Kp, *Vp, *Op;
    cudaGetSymbolAddress((void**)&Qp, g_Q);
    cudaGetSymbolAddress((void**)&Kp, g_K);
    cudaGetSymbolAddress((void**)&Vp, g_V);
    cudaGetSymbolAddress((void**)&Op, g_O);

    cudaFuncSetAttribute(gemm_qkv, cudaFuncAttributeMaxDynamicSharedMemorySize, GEMM_SMEM);
    cudaFuncSetAttribute(gemm_o,   cudaFuncAttributeMaxDynamicSharedMemorySize, GEMM_SMEM);
    cudaFuncSetAttribute(attn_mma, cudaFuncAttributeMaxDynamicSharedMemorySize, ATTN_SMEM);

    // Fused QKV projection (one launch, 384 CTAs).
    gemm_qkv<<<dim3((D_MODEL + 2 * KV_DIM) / 128, BT / 128), 256, GEMM_SMEM>>>(
        x, Wq, bq, Wk, bk, Wv, bv, Qp, Kp, Vp);

    // Causal GQA attention on tensor cores (128-row q tiles).
    attn_mma<<<dim3(TSEQ / 128, N_HEADS, BATCH), 256, ATTN_SMEM>>>();

    // Output projection.
    gemm_o<<<dim3(D_MODEL / 128, BT / 128), 256, GEMM_SMEM>>>(Op, Wo, bo, out);
}

// round 8
// speedup vs baseline: 3.1698x; 1.1164x over previous
#include <cuda_runtime.h>
#include <cuda_bf16.h>
#include <cstdint>

#define D_MODEL 1024
#define KV_DIM 256
#define N_HEADS 16
#define HEAD_DIM 64
#define TSEQ 2048
#define BATCH 2
#define BT (BATCH * TSEQ)
#define KH2 (D_MODEL / 2)   // packed-u32 row stride for K=1024

// Scratch (device globals; no allocation anywhere).
__device__ float g_Q[(size_t)BT * D_MODEL];
__device__ float g_K[(size_t)BT * KV_DIM];
__device__ float g_V[(size_t)BT * KV_DIM];
// packed bf16x2 hi/lo operands
__device__ uint32_t g_xh[(size_t)BT * KH2];
__device__ uint32_t g_xl[(size_t)BT * KH2];
__device__ uint32_t g_Oh[(size_t)BT * KH2];
__device__ uint32_t g_Ol[(size_t)BT * KH2];
__device__ uint32_t g_WqTh[(size_t)D_MODEL * KH2];
__device__ uint32_t g_WqTl[(size_t)D_MODEL * KH2];
__device__ uint32_t g_WkTh[(size_t)KV_DIM * KH2];
__device__ uint32_t g_WkTl[(size_t)KV_DIM * KH2];
__device__ uint32_t g_WvTh[(size_t)KV_DIM * KH2];
__device__ uint32_t g_WvTl[(size_t)KV_DIM * KH2];
__device__ uint32_t g_WoTh[(size_t)D_MODEL * KH2];
__device__ uint32_t g_WoTl[(size_t)D_MODEL * KH2];

// ---------------------------------------------------------------------------
// Helpers
// ---------------------------------------------------------------------------
__device__ __forceinline__ float f2tf32(float v) {
    uint32_t u; asm("cvt.rna.tf32.f32 %0, %1;" : "=r"(u) : "f"(v));
    return __uint_as_float(u);
}

__device__ __forceinline__ void mma1688(float* d, float a0, float a1, float a2,
                                        float a3, float b0, float b1) {
    asm volatile(
        "mma.sync.aligned.m16n8k8.row.col.f32.tf32.tf32.f32 "
        "{%0,%1,%2,%3}, {%4,%5,%6,%7}, {%8,%9}, {%0,%1,%2,%3};"
        : "+f"(d[0]), "+f"(d[1]), "+f"(d[2]), "+f"(d[3])
        : "r"(__float_as_uint(a0)), "r"(__float_as_uint(a1)),
          "r"(__float_as_uint(a2)), "r"(__float_as_uint(a3)),
          "r"(__float_as_uint(b0)), "r"(__float_as_uint(b1)));
}

__device__ __forceinline__ void mma16816(float* d, uint32_t a0, uint32_t a1,
                                         uint32_t a2, uint32_t a3,
                                         uint32_t b0, uint32_t b1) {
    asm volatile(
        "mma.sync.aligned.m16n8k16.row.col.f32.bf16.bf16.f32 "
        "{%0,%1,%2,%3}, {%4,%5,%6,%7}, {%8,%9}, {%0,%1,%2,%3};"
        : "+f"(d[0]), "+f"(d[1]), "+f"(d[2]), "+f"(d[3])
        : "r"(a0), "r"(a1), "r"(a2), "r"(a3), "r"(b0), "r"(b1));
}

__device__ __forceinline__ uint32_t packbf(__nv_bfloat16 a, __nv_bfloat16 b) {
    __nv_bfloat162 t(a, b);   // a -> low 16 bits
    return *reinterpret_cast<uint32_t*>(&t);
}

__device__ __forceinline__ uint32_t smem_u32p(const void* p) {
    uint32_t r;
    asm("{ .reg .u64 t; cvta.to.shared.u64 t, %1; cvt.u32.u64 %0, t; }"
        : "=r"(r) : "l"(p));
    return r;
}

__device__ __forceinline__ void cp16(uint32_t dst, const void* src) {
    asm volatile("cp.async.cg.shared.global [%0], [%1], 16;"
                 :: "r"(dst), "l"(src));
}
#define CP_COMMIT() asm volatile("cp.async.commit_group;" ::: "memory")
#define CP_WAIT0()  asm volatile("cp.async.wait_group 0;" ::: "memory")

// ---------------------------------------------------------------------------
// One-shot converters
// ---------------------------------------------------------------------------
// Pack fp32 -> bf16x2 hi/lo (flat; layout [row][K/2] follows element order).
__global__ __launch_bounds__(256) void conv_pack(
    const float* __restrict__ A, uint32_t* __restrict__ H,
    uint32_t* __restrict__ L, int n4)
{
    int i = blockIdx.x * blockDim.x + threadIdx.x;
    if (i >= n4) return;
    float4 v = ((const float4*)A)[i];
    __nv_bfloat16 hx = __float2bfloat16_rn(v.x);
    __nv_bfloat16 hy = __float2bfloat16_rn(v.y);
    __nv_bfloat16 hz = __float2bfloat16_rn(v.z);
    __nv_bfloat16 hw = __float2bfloat16_rn(v.w);
    ((uint2*)H)[i] = make_uint2(packbf(hx, hy), packbf(hz, hw));
    ((uint2*)L)[i] = make_uint2(
        packbf(__float2bfloat16_rn(v.x - __bfloat162float(hx)),
               __float2bfloat16_rn(v.y - __bfloat162float(hy))),
        packbf(__float2bfloat16_rn(v.z - __bfloat162float(hz)),
               __float2bfloat16_rn(v.w - __bfloat162float(hw))));
}

// W[K][N] -> WT hi/lo [N][K/2] packed (transpose + split).
__global__ __launch_bounds__(256) void conv_wT(
    const float* __restrict__ W, uint32_t* __restrict__ H,
    uint32_t* __restrict__ L, int K, int N)
{
    __shared__ float t[32][33];
    const int n0 = blockIdx.x * 32, k0 = blockIdx.y * 32;
    const int tx = threadIdx.x, ty = threadIdx.y;
#pragma unroll
    for (int i = 0; i < 4; i++)
        t[ty + i * 8][tx] = W[(size_t)(k0 + ty + i * 8) * N + n0 + tx];
    __syncthreads();
#pragma unroll
    for (int i = 0; i < 2; i++) {
        const int kp = ty + i * 8;            // pair index 0..15
        float a = t[kp * 2][tx], b = t[kp * 2 + 1][tx];
        __nv_bfloat16 ha = __float2bfloat16_rn(a);
        __nv_bfloat16 hb = __float2bfloat16_rn(b);
        const size_t o = (size_t)(n0 + tx) * (K / 2) + k0 / 2 + kp;
        H[o] = packbf(ha, hb);
        L[o] = packbf(__float2bfloat16_rn(a - __bfloat162float(ha)),
                      __float2bfloat16_rn(b - __bfloat162float(hb)));
    }
}

// ---------------------------------------------------------------------------
// 2-term bf16-split GEMM on packed operands, cp.async double-buffered.
// C[128,128] at (m0,n0) = A @ W + bias; 256 threads, 64x32 warp tile.
// ---------------------------------------------------------------------------
#define GROW 20
#define G_AH 0
#define G_AL (128 * GROW)
#define G_BH (2 * 128 * GROW)
#define G_BL (3 * 128 * GROW)
#define G_U32 (4 * 128 * GROW)
#define GEMM_SMEM (2 * G_U32 * 4)   // 81920 B (double-buffered)

__device__ __forceinline__ void gemm_stage(
    uint32_t sbase, const uint32_t* __restrict__ AH,
    const uint32_t* __restrict__ AL, const uint32_t* __restrict__ BH,
    const uint32_t* __restrict__ BL, int KH, int m0, int n0, int kc2)
{
    const int tid = threadIdx.x;
#pragma unroll
    for (int j = 0; j < 2; j++) {
        const int idx = tid + j * 256;
        const int r = idx >> 2, sg = (idx & 3) * 4;
        const size_t ao = (size_t)(m0 + r) * KH + kc2 + sg;
        const size_t bo = (size_t)(n0 + r) * KH + kc2 + sg;
        const uint32_t d = sbase + (r * GROW + sg) * 4;
        cp16(d + G_AH * 4, AH + ao);
        cp16(d + G_AL * 4, AL + ao);
        cp16(d + G_BH * 4, BH + bo);
        cp16(d + G_BL * 4, BL + bo);
    }
    CP_COMMIT();
}

__device__ __forceinline__ void gemm_tile_pk(
    const uint32_t* __restrict__ AH, const uint32_t* __restrict__ AL,
    const uint32_t* __restrict__ BH, const uint32_t* __restrict__ BL,
    const float* __restrict__ bias, float* __restrict__ C,
    int N, int KH, int m0, int n0)
{
    extern __shared__ uint32_t su[];
    const uint32_t sbase = smem_u32p(su);

    const int tid = threadIdx.x;
    const int lane = tid & 31;
    const int wid = tid >> 5;
    const int wm = (wid >> 2) * 64;
    const int wn = (wid & 3) * 32;
    const int lr = lane >> 2;
    const int lc = lane & 3;

    float acc[4][4][4];
#pragma unroll
    for (int i = 0; i < 4; i++)
#pragma unroll
        for (int j = 0; j < 4; j++)
#pragma unroll
            for (int k = 0; k < 4; k++) acc[i][j][k] = 0.0f;

    const int NC = KH / 16;   // 32 k per chunk = 16 u32
    int buf = 0;

    gemm_stage(sbase, AH, AL, BH, BL, KH, m0, n0, 0);

    for (int c = 0; c < NC; c++) {
        CP_WAIT0();
        __syncthreads();
        if (c + 1 < NC)
            gemm_stage(sbase + (buf ^ 1) * G_U32 * 4,
                       AH, AL, BH, BL, KH, m0, n0, (c + 1) * 16);

        const uint32_t* sb = su + buf * G_U32;
#pragma unroll
        for (int ss = 0; ss < 2; ss++) {
            const int kp = ss * 8 + lc;
            uint32_t bh[4][2], bl[4][2];
#pragma unroll
            for (int nt = 0; nt < 4; nt++) {
                const int n = wn + nt * 8 + lr;
                bh[nt][0] = sb[G_BH + n * GROW + kp];
                bh[nt][1] = sb[G_BH + n * GROW + kp + 4];
                bl[nt][0] = sb[G_BL + n * GROW + kp];
                bl[nt][1] = sb[G_BL + n * GROW + kp + 4];
            }
#pragma unroll
            for (int mt = 0; mt < 4; mt++) {
                const int m = wm + mt * 16 + lr;
                uint32_t ah0 = sb[G_AH + m * GROW + kp];
                uint32_t ah1 = sb[G_AH + (m + 8) * GROW + kp];
                uint32_t ah2 = sb[G_AH + m * GROW + kp + 4];
                uint32_t ah3 = sb[G_AH + (m + 8) * GROW + kp + 4];
                uint32_t al0 = sb[G_AL + m * GROW + kp];
                uint32_t al1 = sb[G_AL + (m + 8) * GROW + kp];
                uint32_t al2 = sb[G_AL + m * GROW + kp + 4];
                uint32_t al3 = sb[G_AL + (m + 8) * GROW + kp + 4];
#pragma unroll
                for (int nt = 0; nt < 4; nt++) {
                    mma16816(acc[mt][nt], ah0, ah1, ah2, ah3, bh[nt][0], bh[nt][1]);
                    mma16816(acc[mt][nt], ah0, ah1, ah2, ah3, bl[nt][0], bl[nt][1]);
                    mma16816(acc[mt][nt], al0, al1, al2, al3, bh[nt][0], bh[nt][1]);
                }
            }
        }
        buf ^= 1;
    }

#pragma unroll
    for (int nt = 0; nt < 4; nt++) {
        const int n = n0 + wn + nt * 8 + lc * 2;
        const float2 bv = *(const float2*)(bias + n);
#pragma unroll
        for (int mt = 0; mt < 4; mt++) {
            const int m = m0 + wm + mt * 16 + lr;
            float2 o0 = make_float2(acc[mt][nt][0] + bv.x, acc[mt][nt][1] + bv.y);
            float2 o1 = make_float2(acc[mt][nt][2] + bv.x, acc[mt][nt][3] + bv.y);
            *(float2*)(C + (size_t)m * N + n) = o0;
            *(float2*)(C + (size_t)(m + 8) * N + n) = o1;
        }
    }
}

// Fused QKV projection: grid.x covers 1536 output cols (Q:1024 | K:256 | V:256)
__global__ __launch_bounds__(256, 2) void gemm_qkv(
    const float* __restrict__ bq, const float* __restrict__ bk,
    const float* __restrict__ bv,
    float* __restrict__ Q, float* __restrict__ K, float* __restrict__ V)
{
    const int col0 = blockIdx.x * 128;
    const int m0 = blockIdx.y * 128;
    if (col0 < D_MODEL) {
        gemm_tile_pk(g_xh, g_xl, g_WqTh, g_WqTl, bq, Q, D_MODEL, KH2, m0, col0);
    } else if (col0 < D_MODEL + KV_DIM) {
        gemm_tile_pk(g_xh, g_xl, g_WkTh, g_WkTl, bk, K, KV_DIM, KH2, m0, col0 - D_MODEL);
    } else {
        gemm_tile_pk(g_xh, g_xl, g_WvTh, g_WvTl, bv, V, KV_DIM, KH2, m0,
                     col0 - D_MODEL - KV_DIM);
    }
}

__global__ __launch_bounds__(256, 2) void gemm_o(
    const float* __restrict__ bias, float* __restrict__ C)
{
    gemm_tile_pk(g_Oh, g_Ol, g_WoTh, g_WoTl, bias, C, D_MODEL, KH2,
                 blockIdx.y * 128, blockIdx.x * 128);
}

// ---------------------------------------------------------------------------
// Causal GQA flash attention on mma.sync (single tf32). Mainloop proven in R6;
// epilogue now writes packed bf16x2 hi/lo directly (feeds gemm_o).
// ---------------------------------------------------------------------------
#define AT_ST 68
#define ATTN_SMEM (384 * AT_ST * 4)

__global__ __launch_bounds__(256) void attn_mma()
{
    extern __shared__ float sm[];
    float* Qs = sm;
    float* Ks = Qs + 128 * AT_ST;
    float* Vt = Ks + 64 * AT_ST;
    float* Ps = Vt + 64 * AT_ST;

    const int tid = threadIdx.x;
    const int lane = tid & 31;
    const int w = tid >> 5;
    const int lr = lane >> 2;
    const int lc = lane & 3;
    const int qt = blockIdx.x, h = blockIdx.y, b = blockIdx.z;
    const int g = h >> 2;
    const int tb = b * TSEQ;
    const float scale = 0.125f;

    {
        const int r = tid >> 1, c0 = (tid & 1) * 32;
        const float* qr = g_Q + (size_t)(tb + qt * 128 + r) * D_MODEL + h * HEAD_DIM + c0;
        float* dst = Qs + r * AT_ST + c0;
#pragma unroll
        for (int i = 0; i < 8; i++) {
            float4 v = *(const float4*)(qr + i * 4);
            v.x = f2tf32(v.x * scale); v.y = f2tf32(v.y * scale);
            v.z = f2tf32(v.z * scale); v.w = f2tf32(v.w * scale);
            *(float4*)(dst + i * 4) = v;
        }
    }

    float oacc[8][4];
#pragma unroll
    for (int nt = 0; nt < 8; nt++)
#pragma unroll
        for (int j = 0; j < 4; j++) oacc[nt][j] = 0.0f;
    float m0 = -1e30f, m1 = -1e30f, l0 = 0.0f, l1 = 0.0f;

    const int r0 = w * 16 + lr;
    const int qi0 = qt * 128 + r0;
    const int qi1 = qi0 + 8;

    const int nkt = 2 * qt + 2;
    for (int kt = 0; kt < nkt; kt++) {
        __syncthreads();
        {
            const int r = tid >> 2, c0 = (tid & 3) * 16;
            const float* kr = g_K + (size_t)(tb + kt * 64 + r) * KV_DIM + g * HEAD_DIM + c0;
            float* kd = Ks + r * AT_ST + c0;
#pragma unroll
            for (int i = 0; i < 4; i++) {
                float4 v = *(const float4*)(kr + i * 4);
                v.x = f2tf32(v.x); v.y = f2tf32(v.y);
                v.z = f2tf32(v.z); v.w = f2tf32(v.w);
                *(float4*)(kd + i * 4) = v;
            }
            const float* vr = g_V + (size_t)(tb + kt * 64 + r) * KV_DIM + g * HEAD_DIM + c0;
#pragma unroll
            for (int i = 0; i < 4; i++) {
                float4 v = *(const float4*)(vr + i * 4);
                Vt[(c0 + i * 4 + 0) * AT_ST + r] = f2tf32(v.x);
                Vt[(c0 + i * 4 + 1) * AT_ST + r] = f2tf32(v.y);
                Vt[(c0 + i * 4 + 2) * AT_ST + r] = f2tf32(v.z);
                Vt[(c0 + i * 4 + 3) * AT_ST + r] = f2tf32(v.w);
            }
        }
        __syncthreads();

        float sa[8][4];
#pragma unroll
        for (int nt = 0; nt < 8; nt++)
#pragma unroll
            for (int j = 0; j < 4; j++) sa[nt][j] = 0.0f;
#pragma unroll
        for (int kb = 0; kb < 64; kb += 8) {
            const float* q0 = Qs + r0 * AT_ST + kb + lc;
            const float a0 = q0[0];
            const float a1 = q0[8 * AT_ST];
            const float a2 = q0[4];
            const float a3 = q0[8 * AT_ST + 4];
#pragma unroll
            for (int nt = 0; nt < 8; nt++) {
                const float* kk = Ks + (nt * 8 + lr) * AT_ST + kb + lc;
                mma1688(sa[nt], a0, a1, a2, a3, kk[0], kk[4]);
            }
        }

        if (kt >= 2 * qt) {
#pragma unroll
            for (int nt = 0; nt < 8; nt++) {
                const int kj = kt * 64 + nt * 8 + 2 * lc;
                if (kj > qi0)     sa[nt][0] = -1e30f;
                if (kj + 1 > qi0) sa[nt][1] = -1e30f;
                if (kj > qi1)     sa[nt][2] = -1e30f;
                if (kj + 1 > qi1) sa[nt][3] = -1e30f;
            }
        }

        float mx0 = sa[0][0], mx1 = sa[0][2];
#pragma unroll
        for (int nt = 0; nt < 8; nt++) {
            mx0 = fmaxf(mx0, fmaxf(sa[nt][0], sa[nt][1]));
            mx1 = fmaxf(mx1, fmaxf(sa[nt][2], sa[nt][3]));
        }
        mx0 = fmaxf(mx0, __shfl_xor_sync(0xffffffffu, mx0, 1));
        mx0 = fmaxf(mx0, __shfl_xor_sync(0xffffffffu, mx0, 2));
        mx1 = fmaxf(mx1, __shfl_xor_sync(0xffffffffu, mx1, 1));
        mx1 = fmaxf(mx1, __shfl_xor_sync(0xffffffffu, mx1, 2));
        const float nm0 = fmaxf(m0, mx0), nm1 = fmaxf(m1, mx1);
        const float cf0 = __expf(m0 - nm0), cf1 = __expf(m1 - nm1);
        m0 = nm0; m1 = nm1;
        float rs0 = 0.0f, rs1 = 0.0f;
#pragma unroll
        for (int nt = 0; nt < 8; nt++) {
            float p0 = __expf(sa[nt][0] - nm0);
            float p1 = __expf(sa[nt][1] - nm0);
            float p2 = __expf(sa[nt][2] - nm1);
            float p3 = __expf(sa[nt][3] - nm1);
            rs0 += p0 + p1; rs1 += p2 + p3;
            sa[nt][0] = f2tf32(p0); sa[nt][1] = f2tf32(p1);
            sa[nt][2] = f2tf32(p2); sa[nt][3] = f2tf32(p3);
        }
        rs0 += __shfl_xor_sync(0xffffffffu, rs0, 1);
        rs0 += __shfl_xor_sync(0xffffffffu, rs0, 2);
        rs1 += __shfl_xor_sync(0xffffffffu, rs1, 1);
        rs1 += __shfl_xor_sync(0xffffffffu, rs1, 2);
        l0 = l0 * cf0 + rs0;
        l1 = l1 * cf1 + rs1;
#pragma unroll
        for (int nt = 0; nt < 8; nt++) {
            oacc[nt][0] *= cf0; oacc[nt][1] *= cf0;
            oacc[nt][2] *= cf1; oacc[nt][3] *= cf1;
        }

#pragma unroll
        for (int nt = 0; nt < 8; nt++) {
            *(float2*)(Ps + r0 * AT_ST + nt * 8 + 2 * lc) =
                make_float2(sa[nt][0], sa[nt][1]);
            *(float2*)(Ps + (r0 + 8) * AT_ST + nt * 8 + 2 * lc) =
                make_float2(sa[nt][2], sa[nt][3]);
        }
        __syncwarp();

#pragma unroll
        for (int kb = 0; kb < 64; kb += 8) {
            const float* pr = Ps + r0 * AT_ST + kb + lc;
            const float a0 = pr[0];
            const float a1 = pr[8 * AT_ST];
            const float a2 = pr[4];
            const float a3 = pr[8 * AT_ST + 4];
#pragma unroll
            for (int nt = 0; nt < 8; nt++) {
                const float* vv = Vt + (nt * 8 + lr) * AT_ST + kb + lc;
                mma1688(oacc[nt], a0, a1, a2, a3, vv[0], vv[4]);
            }
        }
        __syncwarp();
    }

    // Normalize and write out as packed bf16x2 hi/lo (cols (2lc, 2lc+1) are a k-pair).
    const float inv0 = 1.0f / l0, inv1 = 1.0f / l1;
    const size_t row0 = (size_t)(tb + qt * 128 + r0);
    const int colp = h * 32 + lc;   // pair index base: (h*64 + nt*8 + 2lc)/2
#pragma unroll
    for (int nt = 0; nt < 8; nt++) {
        float v0 = oacc[nt][0] * inv0, v1 = oacc[nt][1] * inv0;
        float v2 = oacc[nt][2] * inv1, v3 = oacc[nt][3] * inv1;
        __nv_bfloat16 h0 = __float2bfloat16_rn(v0);
        __nv_bfloat16 h1 = __float2bfloat16_rn(v1);
        __nv_bfloat16 h2 = __float2bfloat16_rn(v2);
        __nv_bfloat16 h3 = __float2bfloat16_rn(v3);
        const size_t o0 = row0 * KH2 + colp + nt * 4;
        const size_t o1 = (row0 + 8) * KH2 + colp + nt * 4;
        g_Oh[o0] = packbf(h0, h1);
        g_Ol[o0] = packbf(__float2bfloat16_rn(v0 - __bfloat162float(h0)),
                          __float2bfloat16_rn(v1 - __bfloat162float(h1)));
        g_Oh[o1] = packbf(h2, h3);
        g_Ol[o1] = packbf(__float2bfloat16_rn(v2 - __bfloat162float(h2)),
                          __float2bfloat16_rn(v3 - __bfloat162float(h3)));
    }
}

// ---------------------------------------------------------------------------
extern "C" void kernel_launch(void* const* d_in, const int* in_sizes, int n_in,
                              void* d_out, int out_size)
{
    const float* x  = (const float*)d_in[0];
    const float* Wq = (const float*)d_in[1];
    const float* bq = (const float*)d_in[2];
    const float* Wk = (const float*)d_in[3];
    const float* bk = (const float*)d_in[4];
    const float* Wv = (const float*)d_in[5];
    const float* bv = (const float*)d_in[6];
    const float* Wo = (const float*)d_in[7];
    const float* bo = (const float*)d_in[8];
    float* out = (float*)d_out;

    float *Qp, *Kp, *Vp;
    uint32_t *xh, *xl, *WqTh, *WqTl, *WkTh, *WkTl, *WvTh, *WvTl, *WoTh, *WoTl;
    cudaGetSymbolAddress((void**)&Qp, g_Q);
    cudaGetSymbolAddress((void**)&Kp, g_K);
    cudaGetSymbolAddress((void**)&Vp, g_V);
    cudaGetSymbolAddress((void**)&xh, g_xh);
    cudaGetSymbolAddress((void**)&xl, g_xl);
    cudaGetSymbolAddress((void**)&WqTh, g_WqTh);
    cudaGetSymbolAddress((void**)&WqTl, g_WqTl);
    cudaGetSymbolAddress((void**)&WkTh, g_WkTh);
    cudaGetSymbolAddress((void**)&WkTl, g_WkTl);
    cudaGetSymbolAddress((void**)&WvTh, g_WvTh);
    cudaGetSymbolAddress((void**)&WvTl, g_WvTl);
    cudaGetSymbolAddress((void**)&WoTh, g_WoTh);
    cudaGetSymbolAddress((void**)&WoTl, g_WoTl);

    cudaFuncSetAttribute(gemm_qkv, cudaFuncAttributeMaxDynamicSharedMemorySize, GEMM_SMEM);
    cudaFuncSetAttribute(gemm_o,   cudaFuncAttributeMaxDynamicSharedMemorySize, GEMM_SMEM);
    cudaFuncSetAttribute(attn_mma, cudaFuncAttributeMaxDynamicSharedMemorySize, ATTN_SMEM);

    // One-shot conversions.
    conv_pack<<<(BT * D_MODEL / 4 + 255) / 256, 256>>>(x, xh, xl, BT * D_MODEL / 4);
    dim3 wtb(32, 8);
    conv_wT<<<dim3(D_MODEL / 32, D_MODEL / 32), wtb>>>(Wq, WqTh, WqTl, D_MODEL, D_MODEL);
    conv_wT<<<dim3(KV_DIM  / 32, D_MODEL / 32), wtb>>>(Wk, WkTh, WkTl, D_MODEL, KV_DIM);
    conv_wT<<<dim3(KV_DIM  / 32, D_MODEL / 32), wtb>>>(Wv, WvTh, WvTl, D_MODEL, KV_DIM);
    conv_wT<<<dim3(D_MODEL / 32, D_MODEL / 32), wtb>>>(Wo, WoTh, WoTl, D_MODEL, D_MODEL);

    // Fused QKV projection.
    gemm_qkv<<<dim3((D_MODEL + 2 * KV_DIM) / 128, BT / 128), 256, GEMM_SMEM>>>(
        bq, bk, bv, Qp, Kp, Vp);

    // Causal GQA attention (writes packed hi/lo output).
    attn_mma<<<dim3(TSEQ / 128, N_HEADS, BATCH), 256, ATTN_SMEM>>>();

    // Output projection.
    gemm_o<<<dim3(D_MODEL / 128, BT / 128), 256, GEMM_SMEM>>>(bo, out);
}